// round 1
// baseline (speedup 1.0000x reference)
#include <cuda_runtime.h>
#include <cuda_bf16.h>

#define TLEN 512
#define FDIM 1024
#define BDIM 32
#define BLK_THREADS 32
#define UNROLL 8

__device__ __forceinline__ float fast_rcp(float a) {
    float r; asm("rcp.approx.f32 %0, %1;" : "=f"(r) : "f"(a)); return r;
}
__device__ __forceinline__ float fast_sqrt(float a) {
    float r; asm("sqrt.approx.f32 %0, %1;" : "=f"(r) : "f"(a)); return r;
}
__device__ __forceinline__ float fast_ex2(float a) {
    float r; asm("ex2.approx.f32 %0, %1;" : "=f"(r) : "f"(a)); return r;
}

__global__ __launch_bounds__(BLK_THREADS)
void dyn_dense_kernel(const float* __restrict__ x, const float* __restrict__ ws,
                      const float* __restrict__ qs, const float* __restrict__ bias,
                      float* __restrict__ out)
{
    __shared__ float s_invc[TLEN];
    const int tid = threadIdx.x;
    #pragma unroll
    for (int i = tid; i < TLEN; i += BLK_THREADS)
        s_invc[i] = 1.0f / (float)(i + 1);
    __syncthreads();

    // grid = B * (F/32); block of 32 threads covers 32 consecutive f (coalesced)
    const int fblk = blockIdx.x & (FDIM / 32 - 1);
    const int b    = blockIdx.x >> 5;            // FDIM/32 == 32
    const int f    = fblk * 32 + tid;

    // per-aggregation weights: AGGS = (sum, max, mean, var, std)
    const float w0 = ws[0 * FDIM + f];
    const float w1 = ws[1 * FDIM + f];
    const float w2 = ws[2 * FDIM + f];
    const float w3 = ws[3 * FDIM + f];
    const float w4 = ws[4 * FDIM + f];
    const float q0 = qs[0 * FDIM + f];
    const float q1 = qs[1 * FDIM + f];
    const float bz = bias[f];

    const float* xp = x   + (size_t)b * TLEN * FDIM + f;
    float*       op = out + (size_t)b * TLEN * FDIM + f;

    // Keras zero-init states: note max starts at 0.0f (NOT -inf) per reference
    float s = 0.0f, m = 0.0f, ss = 0.0f;
    const float TWO_LOG2E = 2.8853900817779268f;   // 2 / ln(2)

    for (int t0 = 0; t0 < TLEN; t0 += UNROLL) {
        // batched prefetch: 8 independent loads in flight per thread
        float xv[UNROLL];
        #pragma unroll
        for (int u = 0; u < UNROLL; u++)
            xv[u] = __ldg(xp + (size_t)(t0 + u) * FDIM);

        float zv[UNROLL];
        #pragma unroll
        for (int u = 0; u < UNROLL; u++) {
            const int   t  = t0 + u;
            const float xt = xv[u];
            const float c  = (float)(t + 1);
            const float ic = s_invc[t];            // broadcast LDS

            s  += xt;
            ss  = fmaf(xt, xt, ss);
            m   = fmaxf(m, xt);

            const float mean = s * ic;
            const float var  = fmaf(-mean, mean, ss * ic);
            const float stdv = fast_sqrt(var + 1e-4f);

            float z = fmaf(q1, c, q0);             // count polynomial
            z = fmaf(z, c, bz);
            z = fmaf(w0, s,    z);
            z = fmaf(w1, m,    z);
            z = fmaf(w2, mean, z);
            z = fmaf(w3, var,  z);
            z = fmaf(w4, stdv, z);

            // tanh(z) = 1 - 2/(exp(2z)+1); saturates correctly at +/-1
            const float e = fast_ex2(z * TWO_LOG2E);
            const float r = fast_rcp(e + 1.0f);
            zv[u] = fmaf(-2.0f, r, 1.0f);
        }

        #pragma unroll
        for (int u = 0; u < UNROLL; u++)
            op[(size_t)(t0 + u) * FDIM] = zv[u];
    }
}

extern "C" void kernel_launch(void* const* d_in, const int* in_sizes, int n_in,
                              void* d_out, int out_size)
{
    const float* x    = (const float*)d_in[0];
    const float* ws   = (const float*)d_in[1];
    const float* qs   = (const float*)d_in[2];
    const float* bias = (const float*)d_in[3];
    float* out = (float*)d_out;

    const int grid = BDIM * (FDIM / 32);   // 32 * 32 = 1024 blocks
    dyn_dense_kernel<<<grid, BLK_THREADS>>>(x, ws, qs, bias, out);
}

// round 2
// speedup vs baseline: 1.2984x; 1.2984x over previous
#include <cuda_runtime.h>
#include <cuda_bf16.h>

#define TLEN 512
#define FDIM 1024
#define BDIM 32
#define BLK_THREADS 32
#define U 16

__device__ __forceinline__ float fast_rcp(float a) {
    float r; asm("rcp.approx.f32 %0, %1;" : "=f"(r) : "f"(a)); return r;
}
__device__ __forceinline__ float fast_sqrt(float a) {
    float r; asm("sqrt.approx.f32 %0, %1;" : "=f"(r) : "f"(a)); return r;
}
__device__ __forceinline__ float fast_ex2(float a) {
    float r; asm("ex2.approx.f32 %0, %1;" : "=f"(r) : "f"(a)); return r;
}

__global__ __launch_bounds__(BLK_THREADS)
void dyn_dense_kernel(const float* __restrict__ x, const float* __restrict__ ws,
                      const float* __restrict__ qs, const float* __restrict__ bias,
                      float* __restrict__ out)
{
    __shared__ float s_invc[TLEN];
    const int tid = threadIdx.x;
    #pragma unroll
    for (int i = tid; i < TLEN; i += BLK_THREADS)
        s_invc[i] = 1.0f / (float)(i + 1);
    __syncthreads();

    // grid = B * (F/32); one 32-thread block covers 32 consecutive f (coalesced)
    const int fblk = blockIdx.x & (FDIM / 32 - 1);
    const int b    = blockIdx.x >> 5;            // FDIM/32 == 32
    const int f    = fblk * 32 + tid;

    // per-aggregation weights: AGGS = (sum, max, mean, var, std)
    const float w0 = ws[0 * FDIM + f];
    const float w1 = ws[1 * FDIM + f];
    const float w2 = ws[2 * FDIM + f];
    const float w3 = ws[3 * FDIM + f];
    const float w4 = ws[4 * FDIM + f];
    const float q0 = qs[0 * FDIM + f];
    const float q1 = qs[1 * FDIM + f];
    const float bz = bias[f];

    const float* xp = x   + (size_t)b * TLEN * FDIM + f;
    float*       op = out + (size_t)b * TLEN * FDIM + f;

    // Keras zero-init states: max starts at 0.0f (NOT -inf), per reference
    float s = 0.0f, m = 0.0f, ss = 0.0f;
    float c = 0.0f;
    const float TWO_LOG2E = 2.8853900817779268f;   // 2 / ln(2)

    float bufA[U], bufB[U];

    // prologue: fill buffer A with t = 0..U-1
    #pragma unroll
    for (int u = 0; u < U; u++)
        bufA[u] = __ldg(xp + u * FDIM);

    // process one U-batch starting at time t0 from buf[]
    auto compute = [&](const float* buf, int t0) {
        #pragma unroll
        for (int u = 0; u < U; u++) {
            const float xt = buf[u];
            c += 1.0f;
            const float ic = s_invc[t0 + u];       // broadcast LDS

            s  += xt;
            ss  = fmaf(xt, xt, ss);
            m   = fmaxf(m, xt);

            const float mean = s * ic;
            const float var  = fmaf(-mean, mean, ss * ic);
            const float stdv = fast_sqrt(var + 1e-4f);

            float z = fmaf(q1, c, q0);             // count polynomial
            z = fmaf(z, c, bz);
            z = fmaf(w0, s,    z);
            z = fmaf(w1, m,    z);
            z = fmaf(w2, mean, z);
            z = fmaf(w3, var,  z);
            z = fmaf(w4, stdv, z);

            // tanh(z) = 1 - 2/(exp(2z)+1); saturates correctly at +/-1
            const float e = fast_ex2(z * TWO_LOG2E);
            const float r = fast_rcp(e + 1.0f);
            op[(t0 + u) * FDIM] = fmaf(-2.0f, r, 1.0f);
        }
    };

    // double-buffered mainloop: loads for the next batch are in flight
    // while the current batch computes
    for (int t0 = 0; t0 < TLEN; t0 += 2 * U) {
        {   // load B batch at t0+U (always in range: t0+U <= TLEN-U)
            const float* p = xp + (t0 + U) * FDIM;
            #pragma unroll
            for (int u = 0; u < U; u++)
                bufB[u] = __ldg(p + u * FDIM);
        }
        compute(bufA, t0);

        if (t0 + 2 * U < TLEN) {   // load A batch at t0+2U
            const float* p = xp + (t0 + 2 * U) * FDIM;
            #pragma unroll
            for (int u = 0; u < U; u++)
                bufA[u] = __ldg(p + u * FDIM);
        }
        compute(bufB, t0 + U);
    }
}

extern "C" void kernel_launch(void* const* d_in, const int* in_sizes, int n_in,
                              void* d_out, int out_size)
{
    const float* x    = (const float*)d_in[0];
    const float* ws   = (const float*)d_in[1];
    const float* qs   = (const float*)d_in[2];
    const float* bias = (const float*)d_in[3];
    float* out = (float*)d_out;

    const int grid = BDIM * (FDIM / 32);   // 32 * 32 = 1024 blocks
    dyn_dense_kernel<<<grid, BLK_THREADS>>>(x, ws, qs, bias, out);
}

// round 4
// speedup vs baseline: 1.7081x; 1.3155x over previous
#include <cuda_runtime.h>
#include <cuda_bf16.h>

#define TLEN 512
#define FDIM 1024
#define BDIM 32
#define NW   8            // warps per block = time chunks
#define CHUNK (TLEN / NW) // 64 timesteps per warp
#define U    8            // load batch

__device__ __forceinline__ float fast_rcp(float a) {
    float r; asm("rcp.approx.f32 %0, %1;" : "=f"(r) : "f"(a)); return r;
}
__device__ __forceinline__ float fast_sqrt(float a) {
    float r; asm("sqrt.approx.f32 %0, %1;" : "=f"(r) : "f"(a)); return r;
}
__device__ __forceinline__ float fast_ex2(float a) {
    float r; asm("ex2.approx.f32 %0, %1;" : "=f"(r) : "f"(a)); return r;
}

__global__ __launch_bounds__(NW * 32)
void dyn_dense_kernel(const float* __restrict__ x, const float* __restrict__ ws,
                      const float* __restrict__ qs, const float* __restrict__ bias,
                      float* __restrict__ out)
{
    __shared__ float sm_s[NW][32];
    __shared__ float sm_m[NW][32];
    __shared__ float sm_q[NW][32];
    __shared__ float s_invc[TLEN];

    const int tid  = threadIdx.x;
    const int warp = tid >> 5;
    const int lane = tid & 31;

    #pragma unroll
    for (int i = tid; i < TLEN; i += NW * 32)
        s_invc[i] = 1.0f / (float)(i + 1);

    const int fblk = blockIdx.x & (FDIM / 32 - 1);
    const int b    = blockIdx.x >> 5;              // FDIM/32 == 32
    const int f    = fblk * 32 + lane;

    // per-aggregation weights: AGGS = (sum, max, mean, var, std)
    const float w0 = ws[0 * FDIM + f];
    const float w1 = ws[1 * FDIM + f];
    const float w2 = ws[2 * FDIM + f];
    const float w3 = ws[3 * FDIM + f];
    const float w4 = ws[4 * FDIM + f];
    const float q0 = qs[0 * FDIM + f];
    const float q1 = qs[1 * FDIM + f];
    const float bz = bias[f];

    // this warp's chunk base: timesteps [warp*CHUNK, warp*CHUNK + CHUNK)
    const size_t colbase = (size_t)b * TLEN * FDIM + f;
    const float* xp = x   + colbase + (size_t)(warp * CHUNK) * FDIM;
    float*       op = out + colbase + (size_t)(warp * CHUNK) * FDIM;

    // ---- Phase 1: per-chunk partials (sum, max, sumsq) ----
    // max identity is 0.0f: matches Keras zero-init of the max state.
    float ps = 0.0f, pm = 0.0f, pq = 0.0f;
    for (int t0 = 0; t0 < CHUNK; t0 += U) {
        float xv[U];
        #pragma unroll
        for (int u = 0; u < U; u++)
            xv[u] = __ldg(xp + (size_t)(t0 + u) * FDIM);
        #pragma unroll
        for (int u = 0; u < U; u++) {
            ps += xv[u];
            pq  = fmaf(xv[u], xv[u], pq);
            pm  = fmaxf(pm, xv[u]);
        }
    }
    sm_s[warp][lane] = ps;
    sm_m[warp][lane] = pm;
    sm_q[warp][lane] = pq;

    // prefetch first phase-2 batch before the barrier: hides barrier +
    // prefix-combine latency behind 8 in-flight (L2-hot) loads
    float pre[U];
    #pragma unroll
    for (int u = 0; u < U; u++)
        pre[u] = __ldg(xp + (size_t)u * FDIM);

    __syncthreads();

    // ---- Phase 2: exclusive prefix over earlier chunks ----
    float s = 0.0f, m = 0.0f, ss = 0.0f;
    #pragma unroll
    for (int w = 0; w < NW; w++) {
        if (w < warp) {
            s  += sm_s[w][lane];
            m   = fmaxf(m, sm_m[w][lane]);
            ss += sm_q[w][lane];
        }
    }

    float c = (float)(warp * CHUNK);
    const int tbase = warp * CHUNK;
    const float TWO_LOG2E = 2.8853900817779268f;   // 2 / ln(2)

    // sequential scan over this chunk; reloads are L2-hot
    for (int t0 = 0; t0 < CHUNK; t0 += U) {
        float xv[U];
        if (t0 == 0) {
            #pragma unroll
            for (int u = 0; u < U; u++) xv[u] = pre[u];
        } else {
            #pragma unroll
            for (int u = 0; u < U; u++)
                xv[u] = __ldg(xp + (size_t)(t0 + u) * FDIM);
        }

        #pragma unroll
        for (int u = 0; u < U; u++) {
            const float xt = xv[u];
            c += 1.0f;
            const float ic = s_invc[tbase + t0 + u];   // broadcast LDS

            s  += xt;
            ss  = fmaf(xt, xt, ss);
            m   = fmaxf(m, xt);

            const float mean = s * ic;
            const float var  = fmaf(-mean, mean, ss * ic);
            const float stdv = fast_sqrt(var + 1e-4f);

            float z = fmaf(q1, c, q0);                 // count polynomial
            z = fmaf(z, c, bz);
            z = fmaf(w0, s,    z);
            z = fmaf(w1, m,    z);
            z = fmaf(w2, mean, z);
            z = fmaf(w3, var,  z);
            z = fmaf(w4, stdv, z);

            // tanh(z) = 1 - 2/(exp(2z)+1); saturates correctly at +/-1
            const float e = fast_ex2(z * TWO_LOG2E);
            const float r = fast_rcp(e + 1.0f);
            op[(size_t)(t0 + u) * FDIM] = fmaf(-2.0f, r, 1.0f);
        }
    }
}

extern "C" void kernel_launch(void* const* d_in, const int* in_sizes, int n_in,
                              void* d_out, int out_size)
{
    const float* x    = (const float*)d_in[0];
    const float* ws   = (const float*)d_in[1];
    const float* qs   = (const float*)d_in[2];
    const float* bias = (const float*)d_in[3];
    float* out = (float*)d_out;

    const int grid = BDIM * (FDIM / 32);   // 32 * 32 = 1024 blocks
    dyn_dense_kernel<<<grid, NW * 32>>>(x, ws, qs, bias, out);
}

// round 5
// speedup vs baseline: 1.8294x; 1.0710x over previous
#include <cuda_runtime.h>
#include <cuda_bf16.h>

#define TLEN 512
#define FDIM 1024
#define BDIM 32
#define NW    8             // warps per block = time chunks
#define CHUNK (TLEN / NW)   // 64 timesteps per warp
#define U1    8             // phase-1 load batch (DRAM latency)
#define U2    4             // phase-2 load batch (L2-hot)

__device__ __forceinline__ float fast_sqrt(float a) {
    float r; asm("sqrt.approx.f32 %0, %1;" : "=f"(r) : "f"(a)); return r;
}
__device__ __forceinline__ float fast_tanh(float a) {
    float r; asm("tanh.approx.f32 %0, %1;" : "=f"(r) : "f"(a)); return r;
}

__global__ __launch_bounds__(NW * 32, 8)
void dyn_dense_kernel(const float* __restrict__ x, const float* __restrict__ ws,
                      const float* __restrict__ qs, const float* __restrict__ bias,
                      float* __restrict__ out)
{
    __shared__ float sm_s[NW][32];
    __shared__ float sm_m[NW][32];
    __shared__ float sm_q[NW][32];
    __shared__ float s_invc[TLEN];

    const int tid  = threadIdx.x;
    const int warp = tid >> 5;
    const int lane = tid & 31;

    #pragma unroll
    for (int i = tid; i < TLEN; i += NW * 32)
        s_invc[i] = 1.0f / (float)(i + 1);

    const int fblk = blockIdx.x & (FDIM / 32 - 1);
    const int b    = blockIdx.x >> 5;              // FDIM/32 == 32
    const int f    = fblk * 32 + lane;

    // this warp's chunk: timesteps [warp*CHUNK, warp*CHUNK + CHUNK)
    const size_t colbase = (size_t)b * TLEN * FDIM + f + (size_t)(warp * CHUNK) * FDIM;

    // ---- Phase 1: per-chunk partials (sum, max, sumsq) ----
    // max identity is 0.0f: matches Keras zero-init of the max state.
    float ps = 0.0f, pm = 0.0f, pq = 0.0f;
    {
        const float* p = x + colbase;
        #pragma unroll
        for (int t0 = 0; t0 < CHUNK; t0 += U1) {
            float xv[U1];
            #pragma unroll
            for (int u = 0; u < U1; u++)
                xv[u] = __ldg(p + u * FDIM);        // compile-time immediates
            p += U1 * FDIM;
            #pragma unroll
            for (int u = 0; u < U1; u++) {
                ps += xv[u];
                pq  = fmaf(xv[u], xv[u], pq);
                pm  = fmaxf(pm, xv[u]);
            }
        }
    }
    sm_s[warp][lane] = ps;
    sm_m[warp][lane] = pm;
    sm_q[warp][lane] = pq;
    __syncthreads();

    // ---- Phase 2: exclusive prefix over earlier chunks ----
    float s = 0.0f, m = 0.0f, ss = 0.0f;
    #pragma unroll
    for (int w = 0; w < NW; w++) {
        if (w < warp) {
            s  += sm_s[w][lane];
            m   = fmaxf(m, sm_m[w][lane]);
            ss += sm_q[w][lane];
        }
    }

    // per-aggregation weights: AGGS = (sum, max, mean, var, std)
    const float w0 = ws[0 * FDIM + f];
    const float w1 = ws[1 * FDIM + f];
    const float w2 = ws[2 * FDIM + f];
    const float w3 = ws[3 * FDIM + f];
    const float w4 = ws[4 * FDIM + f];
    const float q0 = qs[0 * FDIM + f];
    const float q1 = qs[1 * FDIM + f];
    const float bz = bias[f];

    float c = (float)(warp * CHUNK);
    const float* p = x   + colbase;
    float*       o = out + colbase;
    const float* icp = &s_invc[warp * CHUNK];

    // sequential scan over this chunk; reloads are L2-hot
    #pragma unroll 2
    for (int t0 = 0; t0 < CHUNK; t0 += U2) {
        float xv[U2];
        #pragma unroll
        for (int u = 0; u < U2; u++)
            xv[u] = __ldg(p + u * FDIM);
        p += U2 * FDIM;

        #pragma unroll
        for (int u = 0; u < U2; u++) {
            const float xt = xv[u];
            c += 1.0f;
            const float ic = icp[u];               // broadcast LDS

            s  += xt;
            ss  = fmaf(xt, xt, ss);
            m   = fmaxf(m, xt);

            const float mean = s * ic;
            const float veps = fmaf(-mean, mean, fmaf(ss, ic, 1e-4f)); // var + eps
            const float stdv = fast_sqrt(veps);

            float z = fmaf(q1, c, q0);             // count polynomial
            z = fmaf(z, c, bz);
            z = fmaf(w0, s,    z);
            z = fmaf(w1, m,    z);
            z = fmaf(w2, mean, z);
            z = fmaf(w3, veps, z);                 // w3*(var+eps); eps*w3 ~ 5e-6, under tanh, negligible
            z = fmaf(w4, stdv, z);
            z = fmaf(-w3, 1e-4f, z);               // exact eps correction (keeps var term exact)

            o[u * FDIM] = fast_tanh(z);
        }
        icp += U2;
        o   += U2 * FDIM;
    }
}

extern "C" void kernel_launch(void* const* d_in, const int* in_sizes, int n_in,
                              void* d_out, int out_size)
{
    const float* x    = (const float*)d_in[0];
    const float* ws   = (const float*)d_in[1];
    const float* qs   = (const float*)d_in[2];
    const float* bias = (const float*)d_in[3];
    float* out = (float*)d_out;

    const int grid = BDIM * (FDIM / 32);   // 32 * 32 = 1024 blocks
    dyn_dense_kernel<<<grid, NW * 32>>>(x, ws, qs, bias, out);
}

// round 7
// speedup vs baseline: 1.8975x; 1.0373x over previous
#include <cuda_runtime.h>
#include <cuda_bf16.h>

#define TLEN 512
#define FDIM 1024
#define NW    8             // warps per block = time chunks
#define CHUNK (TLEN / NW)   // 64 timesteps per warp
#define U1    8             // phase-1 load batch (DRAM latency)
#define U2    4             // phase-2 load batch (L2-hot), double-buffered
#define F2    (FDIM / 2)    // row stride in float2

__device__ __forceinline__ float fast_sqrt(float a) {
    float r; asm("sqrt.approx.f32 %0, %1;" : "=f"(r) : "f"(a)); return r;
}
__device__ __forceinline__ float fast_tanh(float a) {
    float r; asm("tanh.approx.f32 %0, %1;" : "=f"(r) : "f"(a)); return r;
}

__global__ __launch_bounds__(NW * 32, 4)
void dyn_dense_kernel(const float* __restrict__ x, const float* __restrict__ ws,
                      const float* __restrict__ qs, const float* __restrict__ bias,
                      float* __restrict__ out)
{
    __shared__ float  s_invc[TLEN];
    __shared__ float2 sm_s[NW][32];
    __shared__ float2 sm_m[NW][32];
    __shared__ float2 sm_q[NW][32];

    const int tid  = threadIdx.x;
    const int warp = tid >> 5;
    const int lane = tid & 31;

    #pragma unroll
    for (int i = tid; i < TLEN; i += NW * 32)
        s_invc[i] = 1.0f / (float)(i + 1);

    // grid = B * (FDIM/64); each block covers 64 consecutive f, 2 per thread
    const int fblk = blockIdx.x & (FDIM / 64 - 1);   // 16 f-tiles
    const int b    = blockIdx.x >> 4;
    const int f0   = fblk * 64 + lane * 2;

    // per-aggregation weights: AGGS = (sum, max, mean, var, std)
    // hoisted above phase 1 so these L2 loads hide in the phase-1 shadow
    const float2 w0 = __ldg((const float2*)(ws + 0 * FDIM + f0));
    const float2 w1 = __ldg((const float2*)(ws + 1 * FDIM + f0));
    const float2 w2 = __ldg((const float2*)(ws + 2 * FDIM + f0));
    const float2 w3 = __ldg((const float2*)(ws + 3 * FDIM + f0));
    const float2 w4 = __ldg((const float2*)(ws + 4 * FDIM + f0));
    const float2 q0 = __ldg((const float2*)(qs + 0 * FDIM + f0));
    const float2 q1 = __ldg((const float2*)(qs + 1 * FDIM + f0));
    const float2 bz = __ldg((const float2*)(bias + f0));

    // this warp's chunk in float2 units (f0 is even -> 8B aligned)
    const size_t colbase2 = ((size_t)b * TLEN * FDIM + (size_t)(warp * CHUNK) * FDIM + f0) >> 1;

    // ---- Phase 1: per-chunk partials (sum, max, sumsq) ----
    // max identity 0.0f matches the Keras zero-init of the max state.
    float2 ps = {0.f, 0.f}, pm = {0.f, 0.f}, pq = {0.f, 0.f};
    {
        const float2* p = (const float2*)x + colbase2;
        #pragma unroll
        for (int t0 = 0; t0 < CHUNK; t0 += U1) {
            float2 xv[U1];
            #pragma unroll
            for (int u = 0; u < U1; u++)
                xv[u] = __ldg(p + u * F2);           // immediates
            p += U1 * F2;
            #pragma unroll
            for (int u = 0; u < U1; u++) {
                ps.x += xv[u].x;           ps.y += xv[u].y;
                pq.x  = fmaf(xv[u].x, xv[u].x, pq.x);
                pq.y  = fmaf(xv[u].y, xv[u].y, pq.y);
                pm.x  = fmaxf(pm.x, xv[u].x);
                pm.y  = fmaxf(pm.y, xv[u].y);
            }
        }
    }
    sm_s[warp][lane] = ps;
    sm_m[warp][lane] = pm;
    sm_q[warp][lane] = pq;
    __syncthreads();

    // ---- Phase 2: exclusive prefix over earlier chunks ----
    float2 s = {0.f, 0.f}, m = {0.f, 0.f}, ss = {0.f, 0.f};
    #pragma unroll
    for (int w = 0; w < NW; w++) {
        if (w < warp) {
            float2 a  = sm_s[w][lane]; s.x += a.x;  s.y += a.y;
            float2 mm = sm_m[w][lane]; m.x = fmaxf(m.x, mm.x); m.y = fmaxf(m.y, mm.y);
            float2 qv = sm_q[w][lane]; ss.x += qv.x; ss.y += qv.y;
        }
    }

    float c = (float)(warp * CHUNK);
    const float2* p = (const float2*)x + colbase2;
    float2*       o = (float2*)out + colbase2;
    const float*  icp = &s_invc[warp * CHUNK];

    float2 bufA[U2], bufB[U2];
    #pragma unroll
    for (int u = 0; u < U2; u++)
        bufA[u] = __ldg(p + u * F2);
    p += U2 * F2;

    // one batch of U2 timesteps from buf[]
    auto compute = [&](const float2* buf) {
        #pragma unroll
        for (int u = 0; u < U2; u++) {
            const float2 xt = buf[u];
            c += 1.0f;
            const float ic = icp[u];               // broadcast LDS, shared by both f

            s.x += xt.x;                     s.y += xt.y;
            ss.x = fmaf(xt.x, xt.x, ss.x);   ss.y = fmaf(xt.y, xt.y, ss.y);
            m.x  = fmaxf(m.x, xt.x);         m.y  = fmaxf(m.y, xt.y);

            const float meanx = s.x * ic,  meany = s.y * ic;
            const float vex = fmaf(-meanx, meanx, fmaf(ss.x, ic, 1e-4f)); // var+eps
            const float vey = fmaf(-meany, meany, fmaf(ss.y, ic, 1e-4f));
            const float sdx = fast_sqrt(vex);
            const float sdy = fast_sqrt(vey);

            float zx = fmaf(q1.x, c, q0.x);        // count polynomial
            float zy = fmaf(q1.y, c, q0.y);
            zx = fmaf(zx, c, bz.x);                zy = fmaf(zy, c, bz.y);
            zx = fmaf(w0.x, s.x,   zx);            zy = fmaf(w0.y, s.y,   zy);
            zx = fmaf(w1.x, m.x,   zx);            zy = fmaf(w1.y, m.y,   zy);
            zx = fmaf(w2.x, meanx, zx);            zy = fmaf(w2.y, meany, zy);
            zx = fmaf(w3.x, vex,   zx);            zy = fmaf(w3.y, vey,   zy);
            zx = fmaf(w4.x, sdx,   zx);            zy = fmaf(w4.y, sdy,   zy);
            zx = fmaf(-w3.x, 1e-4f, zx);           zy = fmaf(-w3.y, 1e-4f, zy); // exact eps correction

            float2 r; r.x = fast_tanh(zx); r.y = fast_tanh(zy);
            o[u * F2] = r;
        }
        icp += U2;
        o   += U2 * F2;
    };

    // double-buffered scan over this chunk; reloads are L2-hot
    for (int t0 = 0; t0 < CHUNK; t0 += 2 * U2) {
        #pragma unroll
        for (int u = 0; u < U2; u++)
            bufB[u] = __ldg(p + u * F2);
        p += U2 * F2;
        compute(bufA);

        if (t0 + 2 * U2 < CHUNK) {
            #pragma unroll
            for (int u = 0; u < U2; u++)
                bufA[u] = __ldg(p + u * F2);
            p += U2 * F2;
        }
        compute(bufB);
    }
}

extern "C" void kernel_launch(void* const* d_in, const int* in_sizes, int n_in,
                              void* d_out, int out_size)
{
    const float* x    = (const float*)d_in[0];
    const float* ws   = (const float*)d_in[1];
    const float* qs   = (const float*)d_in[2];
    const float* bias = (const float*)d_in[3];
    float* out = (float*)d_out;

    const int grid = 32 * (FDIM / 64);   // B * 16 f-tiles = 512 blocks
    dyn_dense_kernel<<<grid, NW * 32>>>(x, ws, qs, bias, out);
}

// round 8
// speedup vs baseline: 1.9453x; 1.0252x over previous
#include <cuda_runtime.h>
#include <cuda_bf16.h>

#define TLEN 512
#define FDIM 1024
#define NW    8             // warps per block = time chunks
#define CHUNK (TLEN / NW)   // 64 timesteps per warp
#define U1    16            // phase-1 load batch (DRAM MLP)
#define U2    4             // phase-2 load batch (L2-hot), double-buffered
#define F2    (FDIM / 2)    // row stride in float2

__device__ __forceinline__ float fast_sqrt(float a) {
    float r; asm("sqrt.approx.f32 %0, %1;" : "=f"(r) : "f"(a)); return r;
}
__device__ __forceinline__ float fast_tanh(float a) {
    float r; asm("tanh.approx.f32 %0, %1;" : "=f"(r) : "f"(a)); return r;
}

__global__ __launch_bounds__(NW * 32, 4)
void dyn_dense_kernel(const float* __restrict__ x, const float* __restrict__ ws,
                      const float* __restrict__ qs, const float* __restrict__ bias,
                      float* __restrict__ out)
{
    __shared__ float  s_invc[TLEN];
    __shared__ float2 sm_s[NW][32];
    __shared__ float2 sm_m[NW][32];
    __shared__ float2 sm_q[NW][32];

    const int tid  = threadIdx.x;
    const int warp = tid >> 5;
    const int lane = tid & 31;

    #pragma unroll
    for (int i = tid; i < TLEN; i += NW * 32)
        s_invc[i] = 1.0f / (float)(i + 1);

    // grid = B * (FDIM/64); each block covers 64 consecutive f, 2 per thread
    const int fblk = blockIdx.x & (FDIM / 64 - 1);   // 16 f-tiles
    const int b    = blockIdx.x >> 4;
    const int f0   = fblk * 64 + lane * 2;

    // this warp's chunk in float2 units (f0 even -> 8B aligned)
    const size_t colbase2 = ((size_t)b * TLEN * FDIM + (size_t)(warp * CHUNK) * FDIM + f0) >> 1;

    float2 bufA[U2], bufB[U2];

    // ---- Phase 1: per-chunk partials (sum, max, sumsq) ----
    // Warp NW-1's partials feed nobody (exclusive prefix) -> skip its pass;
    // it prefetches its first phase-2 batch instead.
    // Max identity 0.0f matches the Keras zero-init of the max state.
    if (warp < NW - 1) {
        float2 ps = {0.f, 0.f}, pm = {0.f, 0.f}, pq = {0.f, 0.f};
        const float2* p = (const float2*)x + colbase2;
        #pragma unroll
        for (int t0 = 0; t0 < CHUNK; t0 += U1) {
            float2 xv[U1];
            #pragma unroll
            for (int u = 0; u < U1; u++)
                xv[u] = __ldg(p + u * F2);           // immediates; 16 LDG.64 in flight
            p += U1 * F2;
            #pragma unroll
            for (int u = 0; u < U1; u++) {
                ps.x += xv[u].x;           ps.y += xv[u].y;
                pq.x  = fmaf(xv[u].x, xv[u].x, pq.x);
                pq.y  = fmaf(xv[u].y, xv[u].y, pq.y);
                pm.x  = fmaxf(pm.x, xv[u].x);
                pm.y  = fmaxf(pm.y, xv[u].y);
            }
        }
        sm_s[warp][lane] = ps;
        sm_m[warp][lane] = pm;
        sm_q[warp][lane] = pq;
    } else {
        const float2* p = (const float2*)x + colbase2;
        #pragma unroll
        for (int u = 0; u < U2; u++)
            bufA[u] = __ldg(p + u * F2);
    }
    __syncthreads();

    // ---- Phase 2: exclusive prefix over earlier chunks ----
    float2 s = {0.f, 0.f}, m = {0.f, 0.f}, ss = {0.f, 0.f};
    #pragma unroll
    for (int w = 0; w < NW - 1; w++) {
        if (w < warp) {
            float2 a  = sm_s[w][lane]; s.x += a.x;  s.y += a.y;
            float2 mm = sm_m[w][lane]; m.x = fmaxf(m.x, mm.x); m.y = fmaxf(m.y, mm.y);
            float2 qv = sm_q[w][lane]; ss.x += qv.x; ss.y += qv.y;
        }
    }

    // per-aggregation weights: AGGS = (sum, max, mean, var, std)
    // loaded HERE (after phase 1) to keep phase-1 register pressure low
    const float2 w0 = __ldg((const float2*)(ws + 0 * FDIM + f0));
    const float2 w1 = __ldg((const float2*)(ws + 1 * FDIM + f0));
    const float2 w2 = __ldg((const float2*)(ws + 2 * FDIM + f0));
    const float2 w3 = __ldg((const float2*)(ws + 3 * FDIM + f0));
    const float2 w4 = __ldg((const float2*)(ws + 4 * FDIM + f0));
    const float2 q0 = __ldg((const float2*)(qs + 0 * FDIM + f0));
    const float2 q1 = __ldg((const float2*)(qs + 1 * FDIM + f0));
    float2 bz = __ldg((const float2*)(bias + f0));
    // fold exact eps-correction into the bias: z uses w3*(var+eps) below
    bz.x = fmaf(-w3.x, 1e-4f, bz.x);
    bz.y = fmaf(-w3.y, 1e-4f, bz.y);

    float c = (float)(warp * CHUNK);
    const float2* p = (const float2*)x + colbase2;
    float2*       o = (float2*)out + colbase2;
    const float*  icp = &s_invc[warp * CHUNK];

    if (warp < NW - 1) {                  // warp NW-1 already has bufA
        #pragma unroll
        for (int u = 0; u < U2; u++)
            bufA[u] = __ldg(p + u * F2);
    }
    p += U2 * F2;

    // one batch of U2 timesteps from buf[]
    auto compute = [&](const float2* buf) {
        #pragma unroll
        for (int u = 0; u < U2; u++) {
            const float2 xt = buf[u];
            c += 1.0f;
            const float ic = icp[u];               // broadcast LDS, shared by both f

            s.x += xt.x;                     s.y += xt.y;
            ss.x = fmaf(xt.x, xt.x, ss.x);   ss.y = fmaf(xt.y, xt.y, ss.y);
            m.x  = fmaxf(m.x, xt.x);         m.y  = fmaxf(m.y, xt.y);

            const float meanx = s.x * ic,  meany = s.y * ic;
            const float vex = fmaf(-meanx, meanx, fmaf(ss.x, ic, 1e-4f)); // var+eps
            const float vey = fmaf(-meany, meany, fmaf(ss.y, ic, 1e-4f));
            const float sdx = fast_sqrt(vex);
            const float sdy = fast_sqrt(vey);

            float zx = fmaf(q1.x, c, q0.x);        // count polynomial
            float zy = fmaf(q1.y, c, q0.y);
            zx = fmaf(zx, c, bz.x);                zy = fmaf(zy, c, bz.y);   // bz holds eps fix
            zx = fmaf(w0.x, s.x,   zx);            zy = fmaf(w0.y, s.y,   zy);
            zx = fmaf(w1.x, m.x,   zx);            zy = fmaf(w1.y, m.y,   zy);
            zx = fmaf(w2.x, meanx, zx);            zy = fmaf(w2.y, meany, zy);
            zx = fmaf(w3.x, vex,   zx);            zy = fmaf(w3.y, vey,   zy);
            zx = fmaf(w4.x, sdx,   zx);            zy = fmaf(w4.y, sdy,   zy);

            float2 r; r.x = fast_tanh(zx); r.y = fast_tanh(zy);
            o[u * F2] = r;
        }
        icp += U2;
        o   += U2 * F2;
    };

    // double-buffered scan over this chunk; reloads are L2-hot
    for (int t0 = 0; t0 < CHUNK; t0 += 2 * U2) {
        #pragma unroll
        for (int u = 0; u < U2; u++)
            bufB[u] = __ldg(p + u * F2);
        p += U2 * F2;
        compute(bufA);

        if (t0 + 2 * U2 < CHUNK) {
            #pragma unroll
            for (int u = 0; u < U2; u++)
                bufA[u] = __ldg(p + u * F2);
            p += U2 * F2;
        }
        compute(bufB);
    }
}

extern "C" void kernel_launch(void* const* d_in, const int* in_sizes, int n_in,
                              void* d_out, int out_size)
{
    const float* x    = (const float*)d_in[0];
    const float* ws   = (const float*)d_in[1];
    const float* qs   = (const float*)d_in[2];
    const float* bias = (const float*)d_in[3];
    float* out = (float*)d_out;

    const int grid = 32 * (FDIM / 64);   // B * 16 f-tiles = 512 blocks
    dyn_dense_kernel<<<grid, NW * 32>>>(x, ws, qs, bias, out);
}

// round 9
// speedup vs baseline: 2.1757x; 1.1184x over previous
#include <cuda_runtime.h>
#include <cuda_bf16.h>

#define TLEN  512
#define FDIM  1024
#define NW    16            // warps per block = time chunks
#define CHUNK (TLEN / NW)   // 32 timesteps per warp
#define SSM   16            // steps staged in smem
#define SRG   16            // steps staged in registers

__device__ __forceinline__ float fast_sqrt(float a) {
    float r; asm("sqrt.approx.f32 %0, %1;" : "=f"(r) : "f"(a)); return r;
}
__device__ __forceinline__ float fast_tanh(float a) {
    float r; asm("tanh.approx.f32 %0, %1;" : "=f"(r) : "f"(a)); return r;
}

__global__ __launch_bounds__(NW * 32, 3)
void dyn_dense_kernel(const float* __restrict__ x, const float* __restrict__ ws,
                      const float* __restrict__ qs, const float* __restrict__ bias,
                      float* __restrict__ out)
{
    __shared__ float s_invc[TLEN];                 // 2 KB
    __shared__ float sm_x[NW][SSM][32];            // 32 KB: staged first half of each chunk
    __shared__ float sm_s[NW][32];                 // 6 KB partials
    __shared__ float sm_m[NW][32];
    __shared__ float sm_q[NW][32];

    const int tid  = threadIdx.x;
    const int warp = tid >> 5;
    const int lane = tid & 31;

    s_invc[tid] = 1.0f / (float)(tid + 1);         // 512 threads, one each

    // grid = B * (FDIM/32); block covers 32 consecutive f, all of T
    const int fblk = blockIdx.x & (FDIM / 32 - 1);
    const int b    = blockIdx.x >> 5;
    const int f    = fblk * 32 + lane;

    const size_t colbase = (size_t)b * TLEN * FDIM + (size_t)(warp * CHUNK) * FDIM + f;
    const float* p = x + colbase;

    // ---- Phase 1: load chunk ONCE; stage half to smem, half to regs ----
    // Max identity 0.0f matches the Keras zero-init of the max state.
    float ps = 0.0f, pm = 0.0f, pq = 0.0f;
    {
        float xv[SSM];
        #pragma unroll
        for (int u = 0; u < SSM; u++)
            xv[u] = __ldg(p + u * FDIM);           // 16 LDGs in flight
        #pragma unroll
        for (int u = 0; u < SSM; u++) {
            sm_x[warp][u][lane] = xv[u];           // conflict-free row store
            ps += xv[u];
            pq  = fmaf(xv[u], xv[u], pq);
            pm  = fmaxf(pm, xv[u]);
        }
    }   // xv dead here -> peak regs stays low
    float xr[SRG];
    #pragma unroll
    for (int u = 0; u < SRG; u++)
        xr[u] = __ldg(p + (SSM + u) * FDIM);
    #pragma unroll
    for (int u = 0; u < SRG; u++) {
        ps += xr[u];
        pq  = fmaf(xr[u], xr[u], pq);
        pm  = fmaxf(pm, xr[u]);
    }
    sm_s[warp][lane] = ps;
    sm_m[warp][lane] = pm;
    sm_q[warp][lane] = pq;
    __syncthreads();

    // ---- Phase 2: exclusive prefix over earlier chunks ----
    float s = 0.0f, m = 0.0f, ss = 0.0f;
    #pragma unroll
    for (int w = 0; w < NW - 1; w++) {
        if (w < warp) {
            s  += sm_s[w][lane];
            m   = fmaxf(m, sm_m[w][lane]);
            ss += sm_q[w][lane];
        }
    }

    // per-aggregation weights: AGGS = (sum, max, mean, var, std)
    const float w0 = __ldg(ws + 0 * FDIM + f);
    const float w1 = __ldg(ws + 1 * FDIM + f);
    const float w2 = __ldg(ws + 2 * FDIM + f);
    const float w3 = __ldg(ws + 3 * FDIM + f);
    const float w4 = __ldg(ws + 4 * FDIM + f);
    const float q0 = __ldg(qs + 0 * FDIM + f);
    const float q1 = __ldg(qs + 1 * FDIM + f);
    // fold exact eps-correction into bias: z-chain uses w3*(var+eps)
    const float bz = fmaf(-w3, 1e-4f, __ldg(bias + f));

    float c = (float)(warp * CHUNK);
    float* o = out + colbase;
    const float* icp = &s_invc[warp * CHUNK];

    // one scan step; emits tanh(z) for timestep (warp*CHUNK + t)
    auto step = [&](float xt, int t) {
        c += 1.0f;
        const float ic = icp[t];                   // broadcast LDS

        s  += xt;
        ss  = fmaf(xt, xt, ss);
        m   = fmaxf(m, xt);

        const float mean = s * ic;
        const float veps = fmaf(-mean, mean, fmaf(ss, ic, 1e-4f)); // var + eps
        const float stdv = fast_sqrt(veps);

        float z = fmaf(q1, c, q0);                 // count polynomial
        z = fmaf(z, c, bz);                        // bz holds eps fix
        z = fmaf(w0, s,    z);
        z = fmaf(w1, m,    z);
        z = fmaf(w2, mean, z);
        z = fmaf(w3, veps, z);
        z = fmaf(w4, stdv, z);

        o[t * FDIM] = fast_tanh(z);
    };

    // steps 0..15 from smem stage (conflict-free row reads), 16..31 from regs.
    // NO global reads in this phase: data was loaded exactly once.
    #pragma unroll
    for (int u = 0; u < SSM; u++)
        step(sm_x[warp][u][lane], u);
    #pragma unroll
    for (int u = 0; u < SRG; u++)
        step(xr[u], SSM + u);
}

extern "C" void kernel_launch(void* const* d_in, const int* in_sizes, int n_in,
                              void* d_out, int out_size)
{
    const float* x    = (const float*)d_in[0];
    const float* ws   = (const float*)d_in[1];
    const float* qs   = (const float*)d_in[2];
    const float* bias = (const float*)d_in[3];
    float* out = (float*)d_out;

    const int grid = 32 * (FDIM / 32);   // B * 32 f-tiles = 1024 blocks
    dyn_dense_kernel<<<grid, NW * 32>>>(x, ws, qs, bias, out);
}